// round 1
// baseline (speedup 1.0000x reference)
#include <cuda_runtime.h>
#include <math_constants.h>

#define N_NODES 100000
#define KNB     32
#define DIM     64
#define OUT_COLS 448   // 3*128 + 64

// scratch feature tables (double buffered: gather_l reads one while fused GEMM writes the other)
__device__ float g_hA[N_NODES * DIM];
__device__ float g_hB[N_NODES * DIM];

// ---------------------------------------------------------------------------
// GEMM0: h = relu(x @ W0 + b0)   (x:[N,64], W0:[64,64])
// Also copies x into out[:, 384:448].
// Block: 256 threads (16x16), tile 64 rows x 64 cols.
// ---------------------------------------------------------------------------
__global__ void gemm0_kernel(const float* __restrict__ x,
                             const float* __restrict__ W,
                             const float* __restrict__ b,
                             float* __restrict__ h,
                             float* __restrict__ out)
{
    __shared__ float Xs[64][65];
    __shared__ float Ws[64][65];

    const int tid  = threadIdx.x;
    const int row0 = blockIdx.x * 64;

    #pragma unroll
    for (int i = tid; i < 64 * 64; i += 256) {
        const int r = i >> 6, c = i & 63;
        const int gr = row0 + r;
        float xv = 0.0f;
        if (gr < N_NODES) {
            xv = x[(size_t)gr * 64 + c];
            out[(size_t)gr * OUT_COLS + 384 + c] = xv;   // pass-through input block
        }
        Xs[r][c] = xv;
        Ws[r][c] = W[i];
    }
    __syncthreads();

    const int tx = tid & 15;   // col group
    const int ty = tid >> 4;   // row group

    float acc[4][4];
    #pragma unroll
    for (int i = 0; i < 4; i++)
        #pragma unroll
        for (int j = 0; j < 4; j++)
            acc[i][j] = b[tx * 4 + j];

    #pragma unroll
    for (int k = 0; k < 64; k++) {
        float a[4], w[4];
        #pragma unroll
        for (int i = 0; i < 4; i++) a[i] = Xs[ty * 4 + i][k];
        #pragma unroll
        for (int j = 0; j < 4; j++) w[j] = Ws[k][tx * 4 + j];
        #pragma unroll
        for (int i = 0; i < 4; i++)
            #pragma unroll
            for (int j = 0; j < 4; j++)
                acc[i][j] = fmaf(a[i], w[j], acc[i][j]);
    }

    #pragma unroll
    for (int i = 0; i < 4; i++) {
        const int gr = row0 + ty * 4 + i;
        if (gr < N_NODES) {
            #pragma unroll
            for (int j = 0; j < 4; j++)
                h[(size_t)gr * DIM + tx * 4 + j] = fmaxf(acc[i][j], 0.0f);
        }
    }
}

// ---------------------------------------------------------------------------
// Fused gather (+ optional next-layer GEMM).
// One warp per node. lane j owns features j and j+32.
//   w_k = exp(-10*d_k);  v = w_k * h_in[nb_k]
//   feats[0:64]  = mean_k(v) - h_in[node]
//   feats[64:128]= max_k(v)  - h_in[node]
// If FUSE: h_out[node] = relu(feats @ Wn + bn)   (Wn: [128,64])
// ---------------------------------------------------------------------------
template <bool FUSE>
__global__ void __launch_bounds__(256)
gather_kernel(const int*   __restrict__ idx,
              const float* __restrict__ dist,
              const float* __restrict__ h_in,
              float*       __restrict__ out,
              int                       col_off,
              const float* __restrict__ Wn,
              const float* __restrict__ bn,
              float*       __restrict__ h_out)
{
    __shared__ float Ws[FUSE ? 128 * 64 : 1];
    __shared__ float bs[FUSE ? 64 : 1];
    __shared__ float feats[8][128];

    if (FUSE) {
        for (int i = threadIdx.x; i < 128 * 64; i += 256) Ws[i] = Wn[i];
        if (threadIdx.x < 64) bs[threadIdx.x] = bn[threadIdx.x];
        __syncthreads();
    }

    const int warp = threadIdx.x >> 5;
    const int lane = threadIdx.x & 31;
    const int node = blockIdx.x * 8 + warp;

    if (node < N_NODES) {
        // lane k owns neighbor k's index + weight; broadcast via shfl
        const int   nb = idx[(size_t)node * KNB + lane];
        const float w  = __expf(-10.0f * dist[(size_t)node * KNB + lane]);

        float sum0 = 0.0f, sum1 = 0.0f;
        float mx0 = -CUDART_INF_F, mx1 = -CUDART_INF_F;

        #pragma unroll 8
        for (int k = 0; k < KNB; k++) {
            const int   nk = __shfl_sync(0xffffffffu, nb, k);
            const float wk = __shfl_sync(0xffffffffu, w,  k);
            const float* hr = h_in + (size_t)nk * DIM;
            const float v0 = wk * hr[lane];
            const float v1 = wk * hr[lane + 32];
            sum0 += v0;  sum1 += v1;
            mx0 = fmaxf(mx0, v0);  mx1 = fmaxf(mx1, v1);
        }

        const float hi0 = h_in[(size_t)node * DIM + lane];
        const float hi1 = h_in[(size_t)node * DIM + lane + 32];

        const float f0 = sum0 * (1.0f / KNB) - hi0;
        const float f1 = sum1 * (1.0f / KNB) - hi1;
        const float f2 = mx0 - hi0;
        const float f3 = mx1 - hi1;

        float* orow = out + (size_t)node * OUT_COLS + col_off;
        orow[lane]      = f0;
        orow[lane + 32] = f1;
        orow[lane + 64] = f2;
        orow[lane + 96] = f3;

        if (FUSE) {
            feats[warp][lane]      = f0;
            feats[warp][lane + 32] = f1;
            feats[warp][lane + 64] = f2;
            feats[warp][lane + 96] = f3;
        }
    }

    if (FUSE) {
        __syncwarp();
        if (node < N_NODES) {
            float acc0 = bs[lane];
            float acc1 = bs[lane + 32];
            #pragma unroll
            for (int c = 0; c < 128; c++) {
                const float fv = feats[warp][c];
                acc0 = fmaf(fv, Ws[c * 64 + lane],      acc0);
                acc1 = fmaf(fv, Ws[c * 64 + lane + 32], acc1);
            }
            h_out[(size_t)node * DIM + lane]      = fmaxf(acc0, 0.0f);
            h_out[(size_t)node * DIM + lane + 32] = fmaxf(acc1, 0.0f);
        }
    }
}

// ---------------------------------------------------------------------------
// inputs (metadata order): x, neighbour_indices, distancesq, W0,b0, W1,b1, W2,b2
// output: [N, 448] = [feats0(128) | feats1(128) | feats2(128) | x(64)]
// ---------------------------------------------------------------------------
extern "C" void kernel_launch(void* const* d_in, const int* in_sizes, int n_in,
                              void* d_out, int out_size)
{
    const float* x    = (const float*)d_in[0];
    const int*   idx  = (const int*)  d_in[1];
    const float* dist = (const float*)d_in[2];
    const float* W0   = (const float*)d_in[3];
    const float* b0   = (const float*)d_in[4];
    const float* W1   = (const float*)d_in[5];
    const float* b1   = (const float*)d_in[6];
    const float* W2   = (const float*)d_in[7];
    const float* b2   = (const float*)d_in[8];
    float* out = (float*)d_out;

    float *hA, *hB;
    cudaGetSymbolAddress((void**)&hA, g_hA);
    cudaGetSymbolAddress((void**)&hB, g_hB);

    const int gemm_blocks   = (N_NODES + 63) / 64;
    const int gather_blocks = (N_NODES + 7) / 8;

    // layer 0 dense
    gemm0_kernel<<<gemm_blocks, 256>>>(x, W0, b0, hA, out);
    // gather0 + dense1
    gather_kernel<true><<<gather_blocks, 256>>>(idx, dist, hA, out, 0,   W1, b1, hB);
    // gather1 + dense2
    gather_kernel<true><<<gather_blocks, 256>>>(idx, dist, hB, out, 128, W2, b2, hA);
    // gather2 (last)
    gather_kernel<false><<<gather_blocks, 256>>>(idx, dist, hA, out, 256, nullptr, nullptr, nullptr);
}

// round 2
// speedup vs baseline: 1.3838x; 1.3838x over previous
#include <cuda_runtime.h>
#include <math_constants.h>

#define N_NODES 100000
#define KNB     32
#define DIM     64
#define OUT_COLS 448   // 3*128 + 64

// scratch feature tables (ping-pong between layers)
__device__ float g_hA[N_NODES * DIM];
__device__ float g_hB[N_NODES * DIM];

// ---------------------------------------------------------------------------
// GEMM0: h = relu(x @ W0 + b0)   (x:[N,64], W0:[64,64])
// Also copies x into out[:, 384:448].
// ---------------------------------------------------------------------------
__global__ void __launch_bounds__(256)
gemm0_kernel(const float* __restrict__ x,
             const float* __restrict__ W,
             const float* __restrict__ b,
             float* __restrict__ h,
             float* __restrict__ out)
{
    __shared__ float Xs[64][65];
    __shared__ float Ws[64][65];

    const int tid  = threadIdx.x;
    const int row0 = blockIdx.x * 64;

    #pragma unroll
    for (int i = tid; i < 64 * 64; i += 256) {
        const int r = i >> 6, c = i & 63;
        const int gr = row0 + r;
        float xv = 0.0f;
        if (gr < N_NODES) {
            xv = x[(size_t)gr * 64 + c];
            out[(size_t)gr * OUT_COLS + 384 + c] = xv;   // pass-through input
        }
        Xs[r][c] = xv;
        Ws[r][c] = W[i];
    }
    __syncthreads();

    const int tx = tid & 15;
    const int ty = tid >> 4;

    float acc[4][4];
    #pragma unroll
    for (int i = 0; i < 4; i++)
        #pragma unroll
        for (int j = 0; j < 4; j++)
            acc[i][j] = b[tx * 4 + j];

    #pragma unroll
    for (int k = 0; k < 64; k++) {
        float a[4], w[4];
        #pragma unroll
        for (int i = 0; i < 4; i++) a[i] = Xs[ty * 4 + i][k];
        #pragma unroll
        for (int j = 0; j < 4; j++) w[j] = Ws[k][tx * 4 + j];
        #pragma unroll
        for (int i = 0; i < 4; i++)
            #pragma unroll
            for (int j = 0; j < 4; j++)
                acc[i][j] = fmaf(a[i], w[j], acc[i][j]);
    }

    #pragma unroll
    for (int i = 0; i < 4; i++) {
        const int gr = row0 + ty * 4 + i;
        if (gr < N_NODES) {
            #pragma unroll
            for (int j = 0; j < 4; j++)
                h[(size_t)gr * DIM + tx * 4 + j] = fmaxf(acc[i][j], 0.0f);
        }
    }
}

// ---------------------------------------------------------------------------
// GEMM128: h = relu(F @ W + b)   F rows live inside `out` (row stride 448,
// 128 contiguous cols at the given offset). W:[128,64].
// Tile: 32 rows x 64 cols, 256 threads, K=128. SMEM = 16KB + 32KB = 48KB.
// ---------------------------------------------------------------------------
__global__ void __launch_bounds__(256)
gemm128_kernel(const float* __restrict__ F,   // out + col_off
               const float* __restrict__ W,
               const float* __restrict__ b,
               float* __restrict__ h)
{
    __shared__ float Fs[32][128];
    __shared__ float Ws[128][64];

    const int tid  = threadIdx.x;
    const int row0 = blockIdx.x * 32;

    #pragma unroll
    for (int i = tid; i < 128 * 64; i += 256)
        Ws[i >> 6][i & 63] = W[i];

    #pragma unroll
    for (int i = tid; i < 32 * 128; i += 256) {
        const int r = i >> 7, c = i & 127;
        const int gr = row0 + r;
        Fs[r][c] = (gr < N_NODES) ? F[(size_t)gr * OUT_COLS + c] : 0.0f;
    }
    __syncthreads();

    const int tx = tid & 15;   // 4 cols each
    const int ty = tid >> 4;   // 2 rows each

    float acc[2][4];
    #pragma unroll
    for (int i = 0; i < 2; i++) {
        #pragma unroll
        for (int j = 0; j < 4; j++) acc[i][j] = b[tx * 4 + j];
    }

    #pragma unroll
    for (int k = 0; k < 128; k++) {
        const float a0 = Fs[ty * 2 + 0][k];
        const float a1 = Fs[ty * 2 + 1][k];
        const float4 w4 = *reinterpret_cast<const float4*>(&Ws[k][tx * 4]);
        acc[0][0] = fmaf(a0, w4.x, acc[0][0]);
        acc[0][1] = fmaf(a0, w4.y, acc[0][1]);
        acc[0][2] = fmaf(a0, w4.z, acc[0][2]);
        acc[0][3] = fmaf(a0, w4.w, acc[0][3]);
        acc[1][0] = fmaf(a1, w4.x, acc[1][0]);
        acc[1][1] = fmaf(a1, w4.y, acc[1][1]);
        acc[1][2] = fmaf(a1, w4.z, acc[1][2]);
        acc[1][3] = fmaf(a1, w4.w, acc[1][3]);
    }

    #pragma unroll
    for (int i = 0; i < 2; i++) {
        const int gr = row0 + ty * 2 + i;
        if (gr < N_NODES) {
            float4 v;
            v.x = fmaxf(acc[i][0], 0.0f);
            v.y = fmaxf(acc[i][1], 0.0f);
            v.z = fmaxf(acc[i][2], 0.0f);
            v.w = fmaxf(acc[i][3], 0.0f);
            *reinterpret_cast<float4*>(&h[(size_t)gr * DIM + tx * 4]) = v;
        }
    }
}

// ---------------------------------------------------------------------------
// Gather: one warp per node, lane j owns features j and j+32.
//   w_k = exp(-10*d_k);  v = w_k * h_in[nb_k]
//   out cols [col_off .. col_off+128) = [mean(v)-h, max(v)-h]
// ---------------------------------------------------------------------------
__global__ void __launch_bounds__(256)
gather_kernel(const int*   __restrict__ idx,
              const float* __restrict__ dist,
              const float* __restrict__ h_in,
              float*       __restrict__ out,
              int                       col_off)
{
    const int warp = threadIdx.x >> 5;
    const int lane = threadIdx.x & 31;
    const int node = blockIdx.x * 8 + warp;
    if (node >= N_NODES) return;

    const int   nb = idx[(size_t)node * KNB + lane];
    const float w  = __expf(-10.0f * dist[(size_t)node * KNB + lane]);

    float sum0 = 0.0f, sum1 = 0.0f;
    float mx0 = -CUDART_INF_F, mx1 = -CUDART_INF_F;

    #pragma unroll 8
    for (int k = 0; k < KNB; k++) {
        const int   nk = __shfl_sync(0xffffffffu, nb, k);
        const float wk = __shfl_sync(0xffffffffu, w,  k);
        const float* hr = h_in + (size_t)nk * DIM;
        const float v0 = wk * hr[lane];
        const float v1 = wk * hr[lane + 32];
        sum0 += v0;  sum1 += v1;
        mx0 = fmaxf(mx0, v0);  mx1 = fmaxf(mx1, v1);
    }

    const float hi0 = h_in[(size_t)node * DIM + lane];
    const float hi1 = h_in[(size_t)node * DIM + lane + 32];

    float* orow = out + (size_t)node * OUT_COLS + col_off;
    orow[lane]      = sum0 * (1.0f / KNB) - hi0;
    orow[lane + 32] = sum1 * (1.0f / KNB) - hi1;
    orow[lane + 64] = mx0 - hi0;
    orow[lane + 96] = mx1 - hi1;
}

// ---------------------------------------------------------------------------
// inputs: x, neighbour_indices, distancesq, W0,b0, W1,b1, W2,b2
// output: [N, 448] = [feats0(128) | feats1(128) | feats2(128) | x(64)]
// ---------------------------------------------------------------------------
extern "C" void kernel_launch(void* const* d_in, const int* in_sizes, int n_in,
                              void* d_out, int out_size)
{
    const float* x    = (const float*)d_in[0];
    const int*   idx  = (const int*)  d_in[1];
    const float* dist = (const float*)d_in[2];
    const float* W0   = (const float*)d_in[3];
    const float* b0   = (const float*)d_in[4];
    const float* W1   = (const float*)d_in[5];
    const float* b1   = (const float*)d_in[6];
    const float* W2   = (const float*)d_in[7];
    const float* b2   = (const float*)d_in[8];
    float* out = (float*)d_out;

    float *hA, *hB;
    cudaGetSymbolAddress((void**)&hA, g_hA);
    cudaGetSymbolAddress((void**)&hB, g_hB);

    const int g0_blocks     = (N_NODES + 63) / 64;
    const int g128_blocks   = (N_NODES + 31) / 32;
    const int gather_blocks = (N_NODES + 7) / 8;

    gemm0_kernel<<<g0_blocks, 256>>>(x, W0, b0, hA, out);
    gather_kernel<<<gather_blocks, 256>>>(idx, dist, hA, out, 0);
    gemm128_kernel<<<g128_blocks, 256>>>(out + 0,   W1, b1, hB);
    gather_kernel<<<gather_blocks, 256>>>(idx, dist, hB, out, 128);
    gemm128_kernel<<<g128_blocks, 256>>>(out + 128, W2, b2, hA);
    gather_kernel<<<gather_blocks, 256>>>(idx, dist, hA, out, 256);
}

// round 3
// speedup vs baseline: 1.6366x; 1.1826x over previous
#include <cuda_runtime.h>
#include <cuda_fp16.h>
#include <math_constants.h>

#define N_NODES 100000
#define KNB     32
#define DIM     64
#define DIM2    32        // DIM/2 half2 per row
#define OUT_COLS 448      // 3*128 + 64

// intermediate feature tables in fp16 (half2-packed), ping-pong
__device__ __half2 g_hA[N_NODES * DIM2];
__device__ __half2 g_hB[N_NODES * DIM2];

// ---------------------------------------------------------------------------
// GEMM0: h = relu(x @ W0 + b0)  (x:[N,64], W0:[64,64]) -> h fp16
// Also copies x into out[:, 384:448].
// ---------------------------------------------------------------------------
__global__ void __launch_bounds__(256)
gemm0_kernel(const float* __restrict__ x,
             const float* __restrict__ W,
             const float* __restrict__ b,
             __half2* __restrict__ h,
             float* __restrict__ out)
{
    __shared__ float Xs[64][65];
    __shared__ float Ws[64][65];

    const int tid  = threadIdx.x;
    const int row0 = blockIdx.x * 64;

    #pragma unroll
    for (int i = tid; i < 64 * 64; i += 256) {
        const int r = i >> 6, c = i & 63;
        const int gr = row0 + r;
        float xv = 0.0f;
        if (gr < N_NODES) {
            xv = x[(size_t)gr * 64 + c];
            out[(size_t)gr * OUT_COLS + 384 + c] = xv;
        }
        Xs[r][c] = xv;
        Ws[r][c] = W[i];
    }
    __syncthreads();

    const int tx = tid & 15;
    const int ty = tid >> 4;

    float acc[4][4];
    #pragma unroll
    for (int i = 0; i < 4; i++)
        #pragma unroll
        for (int j = 0; j < 4; j++)
            acc[i][j] = b[tx * 4 + j];

    #pragma unroll
    for (int k = 0; k < 64; k++) {
        float a[4], w[4];
        #pragma unroll
        for (int i = 0; i < 4; i++) a[i] = Xs[ty * 4 + i][k];
        #pragma unroll
        for (int j = 0; j < 4; j++) w[j] = Ws[k][tx * 4 + j];
        #pragma unroll
        for (int i = 0; i < 4; i++)
            #pragma unroll
            for (int j = 0; j < 4; j++)
                acc[i][j] = fmaf(a[i], w[j], acc[i][j]);
    }

    #pragma unroll
    for (int i = 0; i < 4; i++) {
        const int gr = row0 + ty * 4 + i;
        if (gr < N_NODES) {
            float2 p0 = make_float2(fmaxf(acc[i][0], 0.0f), fmaxf(acc[i][1], 0.0f));
            float2 p1 = make_float2(fmaxf(acc[i][2], 0.0f), fmaxf(acc[i][3], 0.0f));
            h[(size_t)gr * DIM2 + tx * 2 + 0] = __float22half2_rn(p0);
            h[(size_t)gr * DIM2 + tx * 2 + 1] = __float22half2_rn(p1);
        }
    }
}

// ---------------------------------------------------------------------------
// GEMM128: h = relu(F @ W + b)  F rows live inside `out` (stride 448, 128
// contiguous cols). W:[128,64]. Tile 64x64, 4x4 register blocking. h -> fp16.
// ---------------------------------------------------------------------------
__global__ void __launch_bounds__(256)
gemm128_kernel(const float* __restrict__ F,   // out + col_off
               const float* __restrict__ W,
               const float* __restrict__ b,
               __half2* __restrict__ h)
{
    __shared__ float Fs[64][129];
    __shared__ float Ws[128][64];

    const int tid  = threadIdx.x;
    const int row0 = blockIdx.x * 64;

    #pragma unroll
    for (int i = tid; i < 128 * 64; i += 256)
        Ws[i >> 6][i & 63] = W[i];

    #pragma unroll
    for (int i = tid; i < 64 * 128; i += 256) {
        const int r = i >> 7, c = i & 127;
        const int gr = row0 + r;
        Fs[r][c] = (gr < N_NODES) ? F[(size_t)gr * OUT_COLS + c] : 0.0f;
    }
    __syncthreads();

    const int tx = tid & 15;   // 4 cols
    const int ty = tid >> 4;   // 4 rows

    float acc[4][4];
    #pragma unroll
    for (int i = 0; i < 4; i++)
        #pragma unroll
        for (int j = 0; j < 4; j++)
            acc[i][j] = b[tx * 4 + j];

    #pragma unroll 4
    for (int k = 0; k < 128; k++) {
        float a[4];
        #pragma unroll
        for (int i = 0; i < 4; i++) a[i] = Fs[ty * 4 + i][k];
        const float4 w4 = *reinterpret_cast<const float4*>(&Ws[k][tx * 4]);
        #pragma unroll
        for (int i = 0; i < 4; i++) {
            acc[i][0] = fmaf(a[i], w4.x, acc[i][0]);
            acc[i][1] = fmaf(a[i], w4.y, acc[i][1]);
            acc[i][2] = fmaf(a[i], w4.z, acc[i][2]);
            acc[i][3] = fmaf(a[i], w4.w, acc[i][3]);
        }
    }

    #pragma unroll
    for (int i = 0; i < 4; i++) {
        const int gr = row0 + ty * 4 + i;
        if (gr < N_NODES) {
            float2 p0 = make_float2(fmaxf(acc[i][0], 0.0f), fmaxf(acc[i][1], 0.0f));
            float2 p1 = make_float2(fmaxf(acc[i][2], 0.0f), fmaxf(acc[i][3], 0.0f));
            h[(size_t)gr * DIM2 + tx * 2 + 0] = __float22half2_rn(p0);
            h[(size_t)gr * DIM2 + tx * 2 + 1] = __float22half2_rn(p1);
        }
    }
}

// ---------------------------------------------------------------------------
// Gather: one warp per node; lane j owns features 2j, 2j+1 (one half2).
// Per neighbor: warp reads one 128B row (fp16). Accumulate in fp32.
// ---------------------------------------------------------------------------
__global__ void __launch_bounds__(256)
gather_kernel(const int*     __restrict__ idx,
              const float*   __restrict__ dist,
              const __half2* __restrict__ h_in,
              float*         __restrict__ out,
              int                         col_off)
{
    const int warp = threadIdx.x >> 5;
    const int lane = threadIdx.x & 31;
    const int node = blockIdx.x * 8 + warp;
    if (node >= N_NODES) return;

    const int   nb = idx[(size_t)node * KNB + lane];
    const float w  = __expf(-10.0f * dist[(size_t)node * KNB + lane]);

    float sum0 = 0.0f, sum1 = 0.0f;
    float mx0 = -CUDART_INF_F, mx1 = -CUDART_INF_F;

    #pragma unroll 8
    for (int k = 0; k < KNB; k++) {
        const int   nk = __shfl_sync(0xffffffffu, nb, k);
        const float wk = __shfl_sync(0xffffffffu, w,  k);
        const float2 g = __half22float2(h_in[(size_t)nk * DIM2 + lane]);
        const float v0 = wk * g.x;
        const float v1 = wk * g.y;
        sum0 += v0;  sum1 += v1;
        mx0 = fmaxf(mx0, v0);  mx1 = fmaxf(mx1, v1);
    }

    const float2 self = __half22float2(h_in[(size_t)node * DIM2 + lane]);

    float* orow = out + (size_t)node * OUT_COLS + col_off;
    float2 mean2 = make_float2(sum0 * (1.0f / KNB) - self.x,
                               sum1 * (1.0f / KNB) - self.y);
    float2 max2  = make_float2(mx0 - self.x, mx1 - self.y);
    reinterpret_cast<float2*>(orow)[lane]      = mean2;
    reinterpret_cast<float2*>(orow + 64)[lane] = max2;
}

// ---------------------------------------------------------------------------
// inputs: x, neighbour_indices, distancesq, W0,b0, W1,b1, W2,b2
// output: [N, 448] = [feats0(128) | feats1(128) | feats2(128) | x(64)]
// ---------------------------------------------------------------------------
extern "C" void kernel_launch(void* const* d_in, const int* in_sizes, int n_in,
                              void* d_out, int out_size)
{
    const float* x    = (const float*)d_in[0];
    const int*   idx  = (const int*)  d_in[1];
    const float* dist = (const float*)d_in[2];
    const float* W0   = (const float*)d_in[3];
    const float* b0   = (const float*)d_in[4];
    const float* W1   = (const float*)d_in[5];
    const float* b1   = (const float*)d_in[6];
    const float* W2   = (const float*)d_in[7];
    const float* b2   = (const float*)d_in[8];
    float* out = (float*)d_out;

    __half2 *hA, *hB;
    cudaGetSymbolAddress((void**)&hA, g_hA);
    cudaGetSymbolAddress((void**)&hB, g_hB);

    const int g64_blocks    = (N_NODES + 63) / 64;
    const int gather_blocks = (N_NODES + 7) / 8;

    gemm0_kernel<<<g64_blocks, 256>>>(x, W0, b0, hA, out);
    gather_kernel<<<gather_blocks, 256>>>(idx, dist, hA, out, 0);
    gemm128_kernel<<<g64_blocks, 256>>>(out + 0,   W1, b1, hB);
    gather_kernel<<<gather_blocks, 256>>>(idx, dist, hB, out, 128);
    gemm128_kernel<<<g64_blocks, 256>>>(out + 128, W2, b2, hA);
    gather_kernel<<<gather_blocks, 256>>>(idx, dist, hA, out, 256);
}

// round 4
// speedup vs baseline: 2.9425x; 1.7980x over previous
#include <cuda_runtime.h>
#include <cuda_fp16.h>
#include <math_constants.h>

#define N_NODES 100000
#define KNB     32
#define DIM     64
#define DIM2    32        // half2 per feature row
#define OUT_COLS 448      // 3*128 + 64

// intermediate feature tables in fp16 (half2-packed), ping-pong
__device__ __half2 g_hA[N_NODES * DIM2];
__device__ __half2 g_hB[N_NODES * DIM2];

static __device__ __forceinline__ __half2 shfl_xor_h2(__half2 v, int m) {
    unsigned u = *reinterpret_cast<unsigned*>(&v);
    u = __shfl_xor_sync(0xffffffffu, u, m);
    return *reinterpret_cast<__half2*>(&u);
}

static __device__ __forceinline__ void mma16816(float* d,
        unsigned a0, unsigned a1, unsigned a2, unsigned a3,
        unsigned b0, unsigned b1) {
    asm volatile(
        "mma.sync.aligned.m16n8k16.row.col.f32.f16.f16.f32 "
        "{%0,%1,%2,%3},{%4,%5,%6,%7},{%8,%9},{%0,%1,%2,%3};"
        : "+f"(d[0]), "+f"(d[1]), "+f"(d[2]), "+f"(d[3])
        : "r"(a0), "r"(a1), "r"(a2), "r"(a3), "r"(b0), "r"(b1));
}

// ---------------------------------------------------------------------------
// Tensor-core GEMM: h = relu(F @ W + b), F:[N,KD] fp32 (row stride INSTRIDE),
// W:[KD,64] fp32. Inputs rounded to fp16, fp32 accumulate, h stored fp16.
// Block: 128 threads (4 warps), 64 rows; warp does 16 rows x 64 cols.
// PASS: additionally copy F's 64 cols into out[:,384:448] (gemm0 only).
// ---------------------------------------------------------------------------
template<int KD, int INSTRIDE, bool PASS>
__global__ void __launch_bounds__(128)
mma_gemm_kernel(const float* __restrict__ F,
                const float* __restrict__ W,
                const float* __restrict__ b,
                __half2* __restrict__ h,
                float* __restrict__ out)
{
    constexpr int K2    = KD / 2;          // half2 per row
    constexpr int K2LOG = (KD == 64) ? 5 : 6;
    constexpr int AP    = K2 + 4;          // padded row (half2 units)

    __shared__ __half2 As[64 * AP];        // A tile, row-major [row][k2]
    __shared__ __half2 Bs[64 * AP];        // W transposed  [n][k2]
    __shared__ float   bsm[64];

    const int tid  = threadIdx.x;
    const int row0 = blockIdx.x * 64;

    // load A (fp32 -> fp16)
    #pragma unroll
    for (int i = tid; i < 64 * K2; i += 128) {
        const int r  = i >> K2LOG;
        const int c2 = i & (K2 - 1);
        const int gr = row0 + r;
        float2 v = make_float2(0.0f, 0.0f);
        if (gr < N_NODES) {
            v = *reinterpret_cast<const float2*>(&F[(size_t)gr * INSTRIDE + 2 * c2]);
            if (PASS)
                *reinterpret_cast<float2*>(&out[(size_t)gr * OUT_COLS + 384 + 2 * c2]) = v;
        }
        As[r * AP + c2] = __float22half2_rn(v);
    }

    // load W transposed: Bs[n][k2] = {W[2k2][n], W[2k2+1][n]}
    #pragma unroll
    for (int i = tid; i < 64 * K2; i += 128) {
        const int n  = i & 63;
        const int k2 = i >> 6;
        float2 wv = make_float2(W[(2 * k2) * 64 + n], W[(2 * k2 + 1) * 64 + n]);
        Bs[n * AP + k2] = __float22half2_rn(wv);
    }
    if (tid < 64) bsm[tid] = b[tid];
    __syncthreads();

    const int warp = tid >> 5;
    const int lane = tid & 31;
    const int r    = lane >> 2;   // 0..7
    const int qc   = lane & 3;    // 0..3

    const unsigned* Asu = reinterpret_cast<const unsigned*>(As);
    const unsigned* Bsu = reinterpret_cast<const unsigned*>(Bs);

    float acc[8][4];
    #pragma unroll
    for (int nt = 0; nt < 8; nt++)
        #pragma unroll
        for (int j = 0; j < 4; j++) acc[nt][j] = 0.0f;

    const int arow0 = (warp * 16 + r) * AP;
    const int arow1 = arow0 + 8 * AP;

    #pragma unroll
    for (int ks = 0; ks < KD / 16; ks++) {
        const int kb = ks * 8;
        const unsigned a0 = Asu[arow0 + kb + qc];
        const unsigned a1 = Asu[arow1 + kb + qc];
        const unsigned a2 = Asu[arow0 + kb + 4 + qc];
        const unsigned a3 = Asu[arow1 + kb + 4 + qc];
        #pragma unroll
        for (int nt = 0; nt < 8; nt++) {
            const int brow = (nt * 8 + r) * AP;
            const unsigned b0 = Bsu[brow + kb + qc];
            const unsigned b1 = Bsu[brow + kb + 4 + qc];
            mma16816(acc[nt], a0, a1, a2, a3, b0, b1);
        }
    }

    // epilogue: bias + relu -> fp16 table
    const int gr0 = row0 + warp * 16 + r;
    const int gr1 = gr0 + 8;
    #pragma unroll
    for (int nt = 0; nt < 8; nt++) {
        const int n0 = nt * 8 + qc * 2;
        const float bb0 = bsm[n0], bb1 = bsm[n0 + 1];
        if (gr0 < N_NODES) {
            float2 v = make_float2(fmaxf(acc[nt][0] + bb0, 0.0f),
                                   fmaxf(acc[nt][1] + bb1, 0.0f));
            h[(size_t)gr0 * DIM2 + nt * 4 + qc] = __float22half2_rn(v);
        }
        if (gr1 < N_NODES) {
            float2 v = make_float2(fmaxf(acc[nt][2] + bb0, 0.0f),
                                   fmaxf(acc[nt][3] + bb1, 0.0f));
            h[(size_t)gr1 * DIM2 + nt * 4 + qc] = __float22half2_rn(v);
        }
    }
}

// ---------------------------------------------------------------------------
// Gather: one warp per node. Lane (g = lane>>3, c = lane&7): group g handles
// neighbors 4t+g (t=0..7), chunk c = features [8c, 8c+8) as one uint4 of fp16.
// All products are >=0 (relu features x positive weights) -> fp16 accumulation
// is cancellation-free. Cross-group combine via shfl_xor(8), shfl_xor(16).
// ---------------------------------------------------------------------------
__global__ void __launch_bounds__(256)
gather_kernel(const int*     __restrict__ idx,
              const float*   __restrict__ dist,
              const __half2* __restrict__ h_in,
              float*         __restrict__ out,
              int                         col_off)
{
    const int warp = threadIdx.x >> 5;
    const int lane = threadIdx.x & 31;
    const int node = blockIdx.x * 8 + warp;
    if (node >= N_NODES) return;

    const int g = lane >> 3;   // neighbor group 0..3
    const int c = lane & 7;    // feature chunk 0..7

    const int   nb = idx[(size_t)node * KNB + lane];
    const float w  = __expf(-10.0f * dist[(size_t)node * KNB + lane]);

    const __half2 zero = __float2half2_rn(0.0f);
    __half2 sum[4] = {zero, zero, zero, zero};
    __half2 mx[4]  = {zero, zero, zero, zero};   // products >= 0, so 0 is identity

    #pragma unroll
    for (int t = 0; t < 8; t++) {
        const int src = 4 * t + g;
        const int   nk  = __shfl_sync(0xffffffffu, nb, src);
        const float wkf = __shfl_sync(0xffffffffu, w,  src);
        const __half2 wk2 = __float2half2_rn(wkf);

        const uint4 gg = *(reinterpret_cast<const uint4*>(h_in + (size_t)nk * DIM2) + c);
        const __half2* gh = reinterpret_cast<const __half2*>(&gg);
        #pragma unroll
        for (int j = 0; j < 4; j++) {
            const __half2 p = __hmul2(gh[j], wk2);
            sum[j] = __hadd2(sum[j], p);
            mx[j]  = __hmax2(mx[j], p);
        }
    }

    // combine the 4 neighbor groups
    #pragma unroll
    for (int j = 0; j < 4; j++) {
        sum[j] = __hadd2(sum[j], shfl_xor_h2(sum[j], 8));
        mx[j]  = __hmax2(mx[j],  shfl_xor_h2(mx[j],  8));
        sum[j] = __hadd2(sum[j], shfl_xor_h2(sum[j], 16));
        mx[j]  = __hmax2(mx[j],  shfl_xor_h2(mx[j],  16));
    }

    // lanes 0..7 store mean block, lanes 8..15 store max block
    if (g < 2) {
        const uint4 sg = *(reinterpret_cast<const uint4*>(h_in + (size_t)node * DIM2) + c);
        const __half2* sh = reinterpret_cast<const __half2*>(&sg);
        float* orow = out + (size_t)node * OUT_COLS + col_off;

        float res[8];
        if (g == 0) {
            #pragma unroll
            for (int j = 0; j < 4; j++) {
                const float2 sf = __half22float2(sum[j]);
                const float2 se = __half22float2(sh[j]);
                res[2 * j]     = sf.x * (1.0f / KNB) - se.x;
                res[2 * j + 1] = sf.y * (1.0f / KNB) - se.y;
            }
        } else {
            orow += 64;
            #pragma unroll
            for (int j = 0; j < 4; j++) {
                const float2 mf = __half22float2(mx[j]);
                const float2 se = __half22float2(sh[j]);
                res[2 * j]     = mf.x - se.x;
                res[2 * j + 1] = mf.y - se.y;
            }
        }
        reinterpret_cast<float4*>(orow + 8 * c)[0] = make_float4(res[0], res[1], res[2], res[3]);
        reinterpret_cast<float4*>(orow + 8 * c)[1] = make_float4(res[4], res[5], res[6], res[7]);
    }
}

// ---------------------------------------------------------------------------
// inputs: x, neighbour_indices, distancesq, W0,b0, W1,b1, W2,b2
// output: [N, 448] = [feats0(128) | feats1(128) | feats2(128) | x(64)]
// ---------------------------------------------------------------------------
extern "C" void kernel_launch(void* const* d_in, const int* in_sizes, int n_in,
                              void* d_out, int out_size)
{
    const float* x    = (const float*)d_in[0];
    const int*   idx  = (const int*)  d_in[1];
    const float* dist = (const float*)d_in[2];
    const float* W0   = (const float*)d_in[3];
    const float* b0   = (const float*)d_in[4];
    const float* W1   = (const float*)d_in[5];
    const float* b1   = (const float*)d_in[6];
    const float* W2   = (const float*)d_in[7];
    const float* b2   = (const float*)d_in[8];
    float* out = (float*)d_out;

    __half2 *hA, *hB;
    cudaGetSymbolAddress((void**)&hA, g_hA);
    cudaGetSymbolAddress((void**)&hB, g_hB);

    const int gemm_blocks   = (N_NODES + 63) / 64;
    const int gather_blocks = (N_NODES + 7) / 8;

    mma_gemm_kernel<64, 64, true><<<gemm_blocks, 128>>>(x, W0, b0, hA, out);
    gather_kernel<<<gather_blocks, 256>>>(idx, dist, hA, out, 0);
    mma_gemm_kernel<128, OUT_COLS, false><<<gemm_blocks, 128>>>(out + 0, W1, b1, hB, nullptr);
    gather_kernel<<<gather_blocks, 256>>>(idx, dist, hB, out, 128);
    mma_gemm_kernel<128, OUT_COLS, false><<<gemm_blocks, 128>>>(out + 128, W2, b2, hA, nullptr);
    gather_kernel<<<gather_blocks, 256>>>(idx, dist, hA, out, 256);
}